// round 9
// baseline (speedup 1.0000x reference)
#include <cuda_runtime.h>
#include <math_constants.h>

#define BB 32
#define SS 4096
#define HH 1024
#define KSPLIT 64
#define KCH (HH / KSPLIT)   // 16
#define HX 4                 // h-tiles of 256
#define HTW 256              // h-tile width

// Scratch (allocation-free rule: __device__ globals; zero-initialized)
__device__ float g_vp[KSPLIT][BB * HH];   // split-K partials of v = hid @ W (8 MB)
__device__ float g_v[BB * HH];            // reduced v
__device__ unsigned int g_vcnt[HX];       // partials-complete counters
__device__ unsigned int g_vdone[HX];      // reduction-complete counters (for reset)

// ---------------------------------------------------------------------------
// v = hid @ W, single kernel: split-K partials + spin-synchronized reduction.
// R9: KSPLIT 32 -> 64 => grid (4, 64) = 256 blocks (R7/R8's 128 blocks gave
// <1 block/SM — chip-wide MLP starvation was the real limiter, not per-thread
// load scheduling). 32-batch amortization kept (proven necessary in R6).
// All 256 blocks are resident (2/SM) so the intra-kernel spin cannot deadlock.
// bias term dropped (softmax is shift-invariant).
// ---------------------------------------------------------------------------
__global__ void __launch_bounds__(256) v_k(const float* __restrict__ hidden,
                                           const float* __restrict__ W) {
    __shared__ float sh[KCH * BB];  // [k][b], 2 KB
    const int hx = blockIdx.x;
    const int ks = blockIdx.y;
    const int k0 = ks * KCH;
    const int h  = hx * HTW + threadIdx.x;

    for (int i = threadIdx.x; i < KCH * BB; i += 256) {
        int k = i / BB, b = i % BB;
        sh[i] = hidden[b * HH + k0 + k];
    }
    __syncthreads();

    // ---- all KCH W loads in flight (16 regs of wv — fits honestly) ----
    float wv[KCH];
    #pragma unroll
    for (int u = 0; u < KCH; u++)
        wv[u] = W[(size_t)(k0 + u) * HH + h];

    float acc[BB];
    #pragma unroll
    for (int b = 0; b < BB; b++) acc[b] = 0.f;

    #pragma unroll
    for (int u = 0; u < KCH; u++) {
        const float4* hb4 = reinterpret_cast<const float4*>(&sh[u * BB]);
        #pragma unroll
        for (int j = 0; j < BB / 4; j++) {
            float4 hv = hb4[j];                       // broadcast LDS.128
            acc[j * 4 + 0] += hv.x * wv[u];
            acc[j * 4 + 1] += hv.y * wv[u];
            acc[j * 4 + 2] += hv.z * wv[u];
            acc[j * 4 + 3] += hv.w * wv[u];
        }
    }
    #pragma unroll
    for (int b = 0; b < BB; b++)
        g_vp[ks][b * HH + h] = acc[b];

    // ---- publish partials; spin (load + backoff) until hx's 64 blocks done ----
    __threadfence();
    __syncthreads();
    if (threadIdx.x == 0) {
        atomicAdd(&g_vcnt[hx], 1u);    // single atomic per block
        unsigned int c;
        do {
            asm volatile("ld.acquire.gpu.u32 %0, [%1];"
                         : "=r"(c) : "l"(&g_vcnt[hx]) : "memory");
            if (c < KSPLIT) __nanosleep(64);
        } while (c < KSPLIT);
    }
    __syncthreads();

    // ---- reduction: blocks ks < BB reduce batch row b = ks; rest just reset ----
    if (ks < BB) {
        const int idx = ks * HH + h;
        float s = 0.f;
        #pragma unroll
        for (int p = 0; p < KSPLIT; p++) s += __ldcg(&g_vp[p][idx]);  // L2 hits
        g_v[idx] = s;
        __threadfence();
    }

    // ---- last finisher per hx resets counters for the next graph replay ----
    __syncthreads();
    if (threadIdx.x == 0) {
        if (atomicAdd(&g_vdone[hx], 1u) == KSPLIT - 1u) {
            g_vcnt[hx] = 0u;
            g_vdone[hx] = 0u;
        }
    }
}

// ---------------------------------------------------------------------------
// Energies ONLY — R1 structure (81 us @ 84.3% DRAM proven). Untouched.
// grid (SS/32, BB) = (128, 32), block 256 = 8 warps x 4 rows/warp.
// ---------------------------------------------------------------------------
__global__ void score_k(const float* __restrict__ enc, float* __restrict__ out) {
    __shared__ float4 sv[HH / 4];  // v[b] staged, 4 KB
    const int b = blockIdx.y;
    for (int i = threadIdx.x; i < HH / 4; i += 256)
        sv[i] = reinterpret_cast<const float4*>(g_v + b * HH)[i];
    __syncthreads();

    const int w = threadIdx.x >> 5, lane = threadIdx.x & 31;
    const int s0 = blockIdx.x * 32 + w * 4;

    #pragma unroll
    for (int r = 0; r < 4; r++) {
        const int s = s0 + r;
        const float4* row =
            reinterpret_cast<const float4*>(enc + (size_t)b * SS * HH + (size_t)s * HH);
        float acc = 0.f;
        #pragma unroll
        for (int i = 0; i < 8; i++) {
            float4 e = row[lane + i * 32];
            float4 v = sv[lane + i * 32];
            acc += e.x * v.x + e.y * v.y + e.z * v.z + e.w * v.w;
        }
        #pragma unroll
        for (int o = 16; o; o >>= 1) acc += __shfl_xor_sync(0xffffffffu, acc, o);
        if (lane == 0) out[b * SS + s] = acc;
    }
}

// ---------------------------------------------------------------------------
// Softmax in place over each row of 4096. grid BB, block 1024, 4 elems/thread.
// ---------------------------------------------------------------------------
__global__ void softmax_k(float* __restrict__ out) {
    __shared__ float red[32];
    __shared__ float bcast;
    float* row = out + blockIdx.x * SS;
    const int w = threadIdx.x >> 5, lane = threadIdx.x & 31;

    float vals[4];
    float mx = -CUDART_INF_F;
    #pragma unroll
    for (int i = 0; i < 4; i++) {
        vals[i] = row[threadIdx.x + i * 1024];
        mx = fmaxf(mx, vals[i]);
    }
    #pragma unroll
    for (int o = 16; o; o >>= 1) mx = fmaxf(mx, __shfl_xor_sync(0xffffffffu, mx, o));
    if (lane == 0) red[w] = mx;
    __syncthreads();
    if (w == 0) {
        float m = red[lane];
        #pragma unroll
        for (int o = 16; o; o >>= 1) m = fmaxf(m, __shfl_xor_sync(0xffffffffu, m, o));
        if (lane == 0) bcast = m;
    }
    __syncthreads();
    mx = bcast;

    float sum = 0.f;
    #pragma unroll
    for (int i = 0; i < 4; i++) {
        vals[i] = __expf(vals[i] - mx);
        sum += vals[i];
    }
    #pragma unroll
    for (int o = 16; o; o >>= 1) sum += __shfl_xor_sync(0xffffffffu, sum, o);
    if (lane == 0) red[w] = sum;
    __syncthreads();
    if (w == 0) {
        float s = red[lane];
        #pragma unroll
        for (int o = 16; o; o >>= 1) s += __shfl_xor_sync(0xffffffffu, s, o);
        if (lane == 0) bcast = s;
    }
    __syncthreads();
    const float inv = 1.0f / bcast;

    #pragma unroll
    for (int i = 0; i < 4; i++)
        row[threadIdx.x + i * 1024] = vals[i] * inv;
}

extern "C" void kernel_launch(void* const* d_in, const int* in_sizes, int n_in,
                              void* d_out, int out_size) {
    const float* hidden = (const float*)d_in[0];  // [B,1,H]
    const float* enc    = (const float*)d_in[1];  // [B,S,H]
    const float* W      = (const float*)d_in[2];  // [H,H]
    // d_in[3] = bias — unused: constant per row under softmax
    float* out = (float*)d_out;                   // [B,S]

    v_k<<<dim3(HX, KSPLIT), 256>>>(hidden, W);
    score_k<<<dim3(SS / 32, BB), 256>>>(enc, out);
    softmax_k<<<BB, 1024>>>(out);
}